// round 9
// baseline (speedup 1.0000x reference)
#include <cuda_runtime.h>
#include <cuda_fp16.h>
#include <cstdint>

// ---------------------------------------------------------------------------
// Problem constants
// ---------------------------------------------------------------------------
#define B_   4
#define N_   2048
#define C_   256
#define H_   8
#define HD_  32
#define M_   (B_ * N_)          // 8192
#define QKV_OUT (3 * C_)        // 768
#define SCALE 0.17677669529663687f  // 1/sqrt(32)
#define L2E   1.4426950408889634f
#define QSCALE (SCALE * L2E)
#define ELEMS (B_ * H_ * N_ * HD_)  // 2,097,152

#define XE (M_ * C_)            // 2,097,152
#define WE (QKV_OUT * C_)       // 196,608
#define PE (C_ * C_)            // 65,536

__device__ __half g_qh[ELEMS];
__device__ __half g_kh[ELEMS];
__device__ __half g_vh[ELEMS];
__device__ __half g_atth[ELEMS];
__device__ __half g_xh[XE];
__device__ __half g_wh[WE];
__device__ __half g_pwh[PE];

// ---------------------------------------------------------------------------
// helpers
// ---------------------------------------------------------------------------
__device__ __forceinline__ uint32_t smem_u32(const void* p) {
    uint32_t a;
    asm("{ .reg .u64 t; cvta.to.shared.u64 t, %1; cvt.u32.u64 %0, t; }"
        : "=r"(a) : "l"(p));
    return a;
}
__device__ __forceinline__ void ldmx4(uint32_t* r, uint32_t addr) {
    asm volatile("ldmatrix.sync.aligned.m8n8.x4.shared.b16 {%0,%1,%2,%3}, [%4];"
        : "=r"(r[0]), "=r"(r[1]), "=r"(r[2]), "=r"(r[3]) : "r"(addr));
}
__device__ __forceinline__ void ldmx4t(uint32_t* r, uint32_t addr) {
    asm volatile("ldmatrix.sync.aligned.m8n8.x4.trans.shared.b16 {%0,%1,%2,%3}, [%4];"
        : "=r"(r[0]), "=r"(r[1]), "=r"(r[2]), "=r"(r[3]) : "r"(addr));
}
__device__ __forceinline__ void mma16816(float* d,
    uint32_t a0, uint32_t a1, uint32_t a2, uint32_t a3,
    uint32_t b0, uint32_t b1) {
    asm volatile("mma.sync.aligned.m16n8k16.row.col.f32.f16.f16.f32 "
        "{%0,%1,%2,%3}, {%4,%5,%6,%7}, {%8,%9}, {%0,%1,%2,%3};"
        : "+f"(d[0]), "+f"(d[1]), "+f"(d[2]), "+f"(d[3])
        : "r"(a0), "r"(a1), "r"(a2), "r"(a3), "r"(b0), "r"(b1));
}
__device__ __forceinline__ float ex2f(float x) {
    float y;
    asm("ex2.approx.f32 %0, %1;" : "=f"(y) : "f"(x));
    return y;
}
__device__ __forceinline__ void cp16(uint32_t s, const void* g) {
    asm volatile("cp.async.cg.shared.global [%0], [%1], 16;"
        :: "r"(s), "l"(g) : "memory");
}
#define CP_COMMIT() asm volatile("cp.async.commit_group;" ::: "memory")
#define CP_WAIT0()  asm volatile("cp.async.wait_group 0;" ::: "memory")

#define ROWP 40   // halfs per padded smem row (80 bytes) — conflict-free ldmatrix

// ---------------------------------------------------------------------------
// Kernel 0: fp32 -> fp16 pre-convert of x, qkv_w, proj_w
// ---------------------------------------------------------------------------
__global__ __launch_bounds__(256) void conv_kernel(
    const float* __restrict__ x, const float* __restrict__ w,
    const float* __restrict__ pw)
{
    const int i = (blockIdx.x * 256 + threadIdx.x) * 4;
    const float* src; __half* dst; int off;
    if (i < XE)            { src = x;  dst = g_xh;  off = i; }
    else if (i < XE + WE)  { src = w;  dst = g_wh;  off = i - XE; }
    else                   { src = pw; dst = g_pwh; off = i - XE - WE; }
    float4 v = *(const float4*)&src[off];
    *(__half2*)&dst[off + 0] = __floats2half2_rn(v.x, v.y);
    *(__half2*)&dst[off + 2] = __floats2half2_rn(v.z, v.w);
}

// ---------------------------------------------------------------------------
// Kernel 1: QKV GEMM via mma.sync, cp.async double-buffered, fp16 inputs.
//   q scaled by SCALE*log2e (softmax uses ex2).
// ---------------------------------------------------------------------------
__global__ __launch_bounds__(256) void qkv_mma_kernel(const float* __restrict__ bias)
{
    __shared__ __align__(16) __half Ah[2][128][ROWP];
    __shared__ __align__(16) __half Bh[2][64][ROWP];

    const int tid  = threadIdx.x;
    const int lane = tid & 31;
    const int warp = tid >> 5;
    const int wm   = warp & 3;
    const int wn   = warp >> 2;
    const int m0   = blockIdx.y * 128;
    const int n0   = blockIdx.x * 64;

    const uint32_t a_base0 = smem_u32(&Ah[0][0][0]);
    const uint32_t b_base0 = smem_u32(&Bh[0][0][0]);
    const uint32_t a_stride = 128 * ROWP * 2;
    const uint32_t b_stride = 64 * ROWP * 2;

    float acc[2][4][4];
#pragma unroll
    for (int mt = 0; mt < 2; mt++)
#pragma unroll
        for (int nt = 0; nt < 4; nt++)
#pragma unroll
            for (int i = 0; i < 4; i++) acc[mt][nt][i] = 0.f;

    const int arow = tid >> 1;
    const int ach  = tid & 1;
    const int brow = tid >> 2;
    const int bch  = tid & 3;
    const uint32_t a_so = (uint32_t)arow * 80u + (uint32_t)ach * 32u;
    const uint32_t b_so = (uint32_t)brow * 80u + (uint32_t)bch * 16u;
    const __half* agp = g_xh + (m0 + arow) * C_ + ach * 16;
    const __half* bgp = g_wh + (n0 + brow) * C_ + bch * 8;

#define QKV_STAGE(k0, bufn) do { \
        cp16(a_base0 + (bufn) * a_stride + a_so +  0, agp + (k0));       \
        cp16(a_base0 + (bufn) * a_stride + a_so + 16, agp + (k0) + 8);   \
        cp16(b_base0 + (bufn) * b_stride + b_so,      bgp + (k0));       \
    } while (0)

    QKV_STAGE(0, 0); CP_COMMIT();

    int buf = 0;
#pragma unroll
    for (int it = 0; it < 8; it++) {
        CP_WAIT0();
        __syncthreads();
        if (it < 7) { QKV_STAGE((it + 1) * 32, buf ^ 1); CP_COMMIT(); }

        const uint32_t a_base = a_base0 + (uint32_t)buf * a_stride;
        const uint32_t b_base = b_base0 + (uint32_t)buf * b_stride;
        uint32_t bf[4][4];
#pragma unroll
        for (int nt = 0; nt < 4; nt++) {
            uint32_t addr = b_base
                + (uint32_t)((wn * 32 + nt * 8 + (lane & 7)) * (ROWP * 2))
                + (uint32_t)((lane >> 3) * 16);
            ldmx4(bf[nt], addr);
        }
#pragma unroll
        for (int kk = 0; kk < 2; kk++) {
            uint32_t af[2][4];
#pragma unroll
            for (int mt = 0; mt < 2; mt++) {
                uint32_t addr = a_base
                    + (uint32_t)((wm * 32 + mt * 16 + (lane & 15)) * (ROWP * 2))
                    + (uint32_t)((lane >> 4) * 16 + kk * 32);
                ldmx4(af[mt], addr);
            }
#pragma unroll
            for (int mt = 0; mt < 2; mt++)
#pragma unroll
                for (int nt = 0; nt < 4; nt++)
                    mma16816(acc[mt][nt],
                             af[mt][0], af[mt][1], af[mt][2], af[mt][3],
                             bf[nt][kk * 2], bf[nt][kk * 2 + 1]);
        }
        buf ^= 1;
    }

    const int rA = lane >> 2;
    const int c2 = (lane & 3) * 2;
#pragma unroll
    for (int mt = 0; mt < 2; mt++) {
#pragma unroll
        for (int half8 = 0; half8 < 2; half8++) {
            const int m = m0 + wm * 32 + mt * 16 + half8 * 8 + rA;
            const int bb = m >> 11;
            const int n  = m & (N_ - 1);
#pragma unroll
            for (int nt = 0; nt < 4; nt++) {
                const int o = n0 + wn * 32 + nt * 8 + c2;
                float v0 = acc[mt][nt][half8 * 2 + 0] + bias[o];
                float v1 = acc[mt][nt][half8 * 2 + 1] + bias[o + 1];
                const int which = o >> 8;
                const int h = (o >> 5) & 7;
                const int d = o & 31;
                const int idx = (((bb * H_ + h) * N_) + n) * HD_ + d;
                if (which == 0) { v0 *= QSCALE; v1 *= QSCALE; }
                __half2 hv = __floats2half2_rn(v0, v1);
                if (which == 0)      *(__half2*)&g_qh[idx] = hv;
                else if (which == 1) *(__half2*)&g_kh[idx] = hv;
                else                 *(__half2*)&g_vh[idx] = hv;
            }
        }
    }
}

// ---------------------------------------------------------------------------
// Kernel 2: mma.sync fp16 flash attention. 128 q rows/CTA (4 warps, 32/warp),
//   KV tiles of 64 keys, cp.async double-buffered.
//   Interleaved: each 16-key chunk does S-MMA -> exp2 -> PV-MMA (short ph life).
//   Bias LUT fp32 pre-scaled by log2e; q pre-scaled; ex2.approx.
// ---------------------------------------------------------------------------
#define KT 64

__global__ __launch_bounds__(128) void attn_mma_kernel(const float* __restrict__ bt)
{
    __shared__ __align__(16) __half Ks[2][KT][ROWP];
    __shared__ __align__(16) __half Vs[2][KT][ROWP];
    __shared__ float b7s[49];

    const int tid  = threadIdx.x;
    const int lane = tid & 31;
    const int warp = tid >> 5;           // 0..3
    const int bh = blockIdx.y;
    const int q0 = blockIdx.x * 128;
    const long base = (long)bh * N_;

    if (tid < 49) b7s[tid] = bt[(tid / 7) - (tid % 7) + 6] * L2E;

    const uint32_t ks_base0 = smem_u32(&Ks[0][0][0]);
    const uint32_t vs_base0 = smem_u32(&Vs[0][0][0]);
    const uint32_t kv_stride = KT * ROWP * 2;

    const int r  = lane >> 2;
    const int cq = lane & 3;
    const int c2 = cq * 2;

    int qa7[2], qb7[2];
    uint32_t qf[2][8];
    int qrA[2];
#pragma unroll
    for (int mt = 0; mt < 2; mt++) {
        qrA[mt] = q0 + warp * 32 + mt * 16 + r;
        const int qrB = qrA[mt] + 8;
        qa7[mt] = (qrA[mt] % 7) * 7;
        qb7[mt] = (qrB % 7) * 7;
        const uint32_t* qpA = (const uint32_t*)(g_qh + (base + qrA[mt]) * HD_);
        const uint32_t* qpB = (const uint32_t*)(g_qh + (base + qrB) * HD_);
        qf[mt][0] = qpA[cq];      qf[mt][1] = qpB[cq];
        qf[mt][2] = qpA[cq + 4];  qf[mt][3] = qpB[cq + 4];
        qf[mt][4] = qpA[cq + 8];  qf[mt][5] = qpB[cq + 8];
        qf[mt][6] = qpA[cq + 12]; qf[mt][7] = qpB[cq + 12];
    }

    float oacc[2][4][4];
#pragma unroll
    for (int mt = 0; mt < 2; mt++)
#pragma unroll
        for (int n = 0; n < 4; n++)
#pragma unroll
            for (int i = 0; i < 4; i++) oacc[mt][n][i] = 0.f;
    float lA[2] = {0.f, 0.f}, lB[2] = {0.f, 0.f};

    // staging: 128 threads, 64 rows x 2 chunks of 16B per tensor
    const int sj = tid >> 1;
    const int sh = tid & 1;
    const uint32_t s_so = (uint32_t)sj * 80u + (uint32_t)sh * 32u;
    const __half* kgp = g_kh + (base + sj) * HD_ + sh * 16;
    const __half* vgp = g_vh + (base + sj) * HD_ + sh * 16;

#define ATT_STAGE(t, bufn) do { \
        cp16(ks_base0 + (bufn) * kv_stride + s_so +  0, kgp + (long)(t) * HD_);     \
        cp16(ks_base0 + (bufn) * kv_stride + s_so + 16, kgp + (long)(t) * HD_ + 8); \
        cp16(vs_base0 + (bufn) * kv_stride + s_so +  0, vgp + (long)(t) * HD_);     \
        cp16(vs_base0 + (bufn) * kv_stride + s_so + 16, vgp + (long)(t) * HD_ + 8); \
    } while (0)

    ATT_STAGE(0, 0); CP_COMMIT();

    int buf = 0;
#pragma unroll 1
    for (int it = 0; it < N_ / KT; it++) {
        CP_WAIT0();
        __syncthreads();
        if (it < N_ / KT - 1) { ATT_STAGE((it + 1) * KT, buf ^ 1); CP_COMMIT(); }

        const int t = it * KT;
        const uint32_t ks_base = ks_base0 + (uint32_t)buf * kv_stride;
        const uint32_t vs_base = vs_base0 + (uint32_t)buf * kv_stride;

        int jm = (t + c2) % 7;
        // 4 chunks of 16 keys; each: S-MMA pair -> exp2 -> PV k-step
#pragma unroll
        for (int kt = 0; kt < 4; kt++) {
            uint32_t ph[2][2][2];   // [jj][mt][frag], live only within chunk
#pragma unroll
            for (int jj = 0; jj < 2; jj++) {
                const int jt = kt * 2 + jj;
                uint32_t kf[4];
                uint32_t addr = ks_base + (uint32_t)((jt * 8 + (lane & 7)) * (ROWP * 2))
                              + (uint32_t)((lane >> 3) * 16);
                ldmx4(kf, addr);
                float sa[2][4];
#pragma unroll
                for (int mt = 0; mt < 2; mt++) {
                    sa[mt][0] = sa[mt][1] = sa[mt][2] = sa[mt][3] = 0.f;
                    mma16816(sa[mt], qf[mt][0], qf[mt][1], qf[mt][2], qf[mt][3], kf[0], kf[1]);
                    mma16816(sa[mt], qf[mt][4], qf[mt][5], qf[mt][6], qf[mt][7], kf[2], kf[3]);
                }
                int jm1 = jm + 1; if (jm1 == 7) jm1 = 0;
#pragma unroll
                for (int mt = 0; mt < 2; mt++) {
                    float p0 = ex2f(sa[mt][0] + b7s[qa7[mt] + jm]);
                    float p1 = ex2f(sa[mt][1] + b7s[qa7[mt] + jm1]);
                    float p2 = ex2f(sa[mt][2] + b7s[qb7[mt] + jm]);
                    float p3 = ex2f(sa[mt][3] + b7s[qb7[mt] + jm1]);
                    lA[mt] += p0 + p1;
                    lB[mt] += p2 + p3;
                    __half2 hA = __floats2half2_rn(p0, p1);
                    __half2 hB = __floats2half2_rn(p2, p3);
                    ph[jj][mt][0] = *reinterpret_cast<uint32_t*>(&hA);
                    ph[jj][mt][1] = *reinterpret_cast<uint32_t*>(&hB);
                }
                jm = jm1;
            }
            // PV for these 16 keys
#pragma unroll
            for (int ntp = 0; ntp < 2; ntp++) {
                uint32_t vf[4];
                uint32_t row = (uint32_t)(kt * 16 + ((lane >> 3) & 1) * 8 + (lane & 7));
                uint32_t col = (uint32_t)(ntp * 16 + (lane >> 4) * 8);
                uint32_t addr = vs_base + row * (ROWP * 2) + col * 2;
                ldmx4t(vf, addr);
#pragma unroll
                for (int mt = 0; mt < 2; mt++) {
                    mma16816(oacc[mt][ntp * 2 + 0],
                             ph[0][mt][0], ph[0][mt][1],
                             ph[1][mt][0], ph[1][mt][1],
                             vf[0], vf[1]);
                    mma16816(oacc[mt][ntp * 2 + 1],
                             ph[0][mt][0], ph[0][mt][1],
                             ph[1][mt][0], ph[1][mt][1],
                             vf[2], vf[3]);
                }
            }
        }
        buf ^= 1;
    }

#pragma unroll
    for (int mt = 0; mt < 2; mt++) {
        float la = lA[mt], lb = lB[mt];
        la += __shfl_xor_sync(0xffffffffu, la, 1);
        la += __shfl_xor_sync(0xffffffffu, la, 2);
        lb += __shfl_xor_sync(0xffffffffu, lb, 1);
        lb += __shfl_xor_sync(0xffffffffu, lb, 2);
        const float invA = 1.f / la;
        const float invB = 1.f / lb;
        __half* opA = g_atth + (base + qrA[mt]) * HD_;
        __half* opB = g_atth + (base + qrA[mt] + 8) * HD_;
#pragma unroll
        for (int nt = 0; nt < 4; nt++) {
            __half2 va = __floats2half2_rn(oacc[mt][nt][0] * invA, oacc[mt][nt][1] * invA);
            __half2 vb = __floats2half2_rn(oacc[mt][nt][2] * invB, oacc[mt][nt][3] * invB);
            *(__half2*)&opA[nt * 8 + c2] = va;
            *(__half2*)&opB[nt * 8 + c2] = vb;
        }
    }
}

// ---------------------------------------------------------------------------
// Kernel 3: proj GEMM via mma.sync, cp.async double-buffered, fp16 inputs.
// ---------------------------------------------------------------------------
__global__ __launch_bounds__(256) void proj_mma_kernel(
    const float* __restrict__ bias, float* __restrict__ out)
{
    __shared__ __align__(16) __half Ah[2][128][ROWP];
    __shared__ __align__(16) __half Bh[2][64][ROWP];

    const int tid  = threadIdx.x;
    const int lane = tid & 31;
    const int warp = tid >> 5;
    const int wm   = warp & 3;
    const int wn   = warp >> 2;
    const int m0   = blockIdx.y * 128;
    const int n0   = blockIdx.x * 64;

    const uint32_t a_base0 = smem_u32(&Ah[0][0][0]);
    const uint32_t b_base0 = smem_u32(&Bh[0][0][0]);
    const uint32_t a_stride = 128 * ROWP * 2;
    const uint32_t b_stride = 64 * ROWP * 2;

    float acc[2][4][4];
#pragma unroll
    for (int mt = 0; mt < 2; mt++)
#pragma unroll
        for (int nt = 0; nt < 4; nt++)
#pragma unroll
            for (int i = 0; i < 4; i++) acc[mt][nt][i] = 0.f;

    const int arow = tid >> 1;
    const int ach  = tid & 1;
    const int brow = tid >> 2;
    const int bch  = tid & 3;
    const uint32_t a_so = (uint32_t)arow * 80u + (uint32_t)ach * 32u;
    const uint32_t b_so = (uint32_t)brow * 80u + (uint32_t)bch * 16u;

    const int m  = m0 + arow;
    const int bb = m >> 11;
    const int nn = m & (N_ - 1);
    const __half* agp = g_atth + ((long)bb * H_ * N_ + nn) * HD_ + ach * 16;
    const __half* bgp = g_pwh + (n0 + brow) * C_ + bch * 8;

#define PROJ_STAGE(h, bufn) do { \
        cp16(a_base0 + (bufn) * a_stride + a_so +  0, agp + (long)(h) * N_ * HD_);     \
        cp16(a_base0 + (bufn) * a_stride + a_so + 16, agp + (long)(h) * N_ * HD_ + 8); \
        cp16(b_base0 + (bufn) * b_stride + b_so,      bgp + (h) * 32);                 \
    } while (0)

    PROJ_STAGE(0, 0); CP_COMMIT();

    int buf = 0;
#pragma unroll
    for (int it = 0; it < 8; it++) {
        CP_WAIT0();
        __syncthreads();
        if (it < 7) { PROJ_STAGE(it + 1, buf ^ 1); CP_COMMIT(); }

        const uint32_t a_base = a_base0 + (uint32_t)buf * a_stride;
        const uint32_t b_base = b_base0 + (uint32_t)buf * b_stride;
        uint32_t bf[4][4];
#pragma unroll
        for (int nt = 0; nt < 4; nt++) {
            uint32_t addr = b_base
                + (uint32_t)((wn * 32 + nt * 8 + (lane & 7)) * (ROWP * 2))
                + (uint32_t)((lane >> 3) * 16);
            ldmx4(bf[nt], addr);
        }
#pragma unroll
        for (int kk = 0; kk < 2; kk++) {
            uint32_t af[2][4];
#pragma unroll
            for (int mt = 0; mt < 2; mt++) {
                uint32_t addr = a_base
                    + (uint32_t)((wm * 32 + mt * 16 + (lane & 15)) * (ROWP * 2))
                    + (uint32_t)((lane >> 4) * 16 + kk * 32);
                ldmx4(af[mt], addr);
            }
#pragma unroll
            for (int mt = 0; mt < 2; mt++)
#pragma unroll
                for (int nt = 0; nt < 4; nt++)
                    mma16816(acc[mt][nt],
                             af[mt][0], af[mt][1], af[mt][2], af[mt][3],
                             bf[nt][kk * 2], bf[nt][kk * 2 + 1]);
        }
        buf ^= 1;
    }

    const int rA = lane >> 2;
    const int c2 = (lane & 3) * 2;
#pragma unroll
    for (int mt = 0; mt < 2; mt++) {
#pragma unroll
        for (int half8 = 0; half8 < 2; half8++) {
            const int mm = m0 + wm * 32 + mt * 16 + half8 * 8 + rA;
#pragma unroll
            for (int nt = 0; nt < 4; nt++) {
                const int o = n0 + wn * 32 + nt * 8 + c2;
                float2 v;
                v.x = acc[mt][nt][half8 * 2 + 0] + bias[o];
                v.y = acc[mt][nt][half8 * 2 + 1] + bias[o + 1];
                *(float2*)&out[mm * C_ + o] = v;
            }
        }
    }
}

// ---------------------------------------------------------------------------
// Launch
// ---------------------------------------------------------------------------
extern "C" void kernel_launch(void* const* d_in, const int* in_sizes, int n_in,
                              void* d_out, int out_size)
{
    const float* x      = (const float*)d_in[0];
    const float* qkv_w  = (const float*)d_in[1];
    const float* qkv_b  = (const float*)d_in[2];
    const float* proj_w = (const float*)d_in[3];
    const float* proj_b = (const float*)d_in[4];
    const float* btab   = (const float*)d_in[5];
    float* out = (float*)d_out;

    (void)in_sizes; (void)n_in; (void)out_size;

    conv_kernel<<<(XE + WE + PE) / (256 * 4), 256>>>(x, qkv_w, proj_w);

    dim3 g1(QKV_OUT / 64, M_ / 128);       // (12, 64)
    qkv_mma_kernel<<<g1, 256>>>(qkv_b);

    dim3 g2(N_ / 128, B_ * H_);            // (16, 32)
    attn_mma_kernel<<<g2, 128>>>(btab);

    dim3 g3(C_ / 64, M_ / 128);            // (4, 64)
    proj_mma_kernel<<<g3, 256>>>(proj_b, out);
}

// round 10
// speedup vs baseline: 1.0839x; 1.0839x over previous
#include <cuda_runtime.h>
#include <cuda_fp16.h>
#include <cstdint>

// ---------------------------------------------------------------------------
// Problem constants
// ---------------------------------------------------------------------------
#define B_   4
#define N_   2048
#define C_   256
#define H_   8
#define HD_  32
#define M_   (B_ * N_)          // 8192
#define QKV_OUT (3 * C_)        // 768
#define SCALE 0.17677669529663687f  // 1/sqrt(32)
#define L2E   1.4426950408889634f
#define QSCALE (SCALE * L2E)
#define ELEMS (B_ * H_ * N_ * HD_)  // 2,097,152
#define NR    (B_ * H_ * N_)        // 65536 (bh,row) pairs

#define XE (M_ * C_)            // 2,097,152
#define WE (QKV_OUT * C_)       // 196,608
#define PE (C_ * C_)            // 65,536

__device__ __half g_qh[ELEMS];
__device__ __half g_kh[ELEMS];
__device__ __half g_vh[ELEMS];
__device__ __half g_atth[ELEMS];
__device__ __half g_xh[XE];
__device__ __half g_wh[WE];
__device__ __half g_pwh[PE];
__device__ float  g_attO[2 * NR * HD_];   // split-KV unnormalized partials
__device__ float  g_attL[2 * NR];

// ---------------------------------------------------------------------------
// helpers
// ---------------------------------------------------------------------------
__device__ __forceinline__ uint32_t smem_u32(const void* p) {
    uint32_t a;
    asm("{ .reg .u64 t; cvta.to.shared.u64 t, %1; cvt.u32.u64 %0, t; }"
        : "=r"(a) : "l"(p));
    return a;
}
__device__ __forceinline__ void ldmx4(uint32_t* r, uint32_t addr) {
    asm volatile("ldmatrix.sync.aligned.m8n8.x4.shared.b16 {%0,%1,%2,%3}, [%4];"
        : "=r"(r[0]), "=r"(r[1]), "=r"(r[2]), "=r"(r[3]) : "r"(addr));
}
__device__ __forceinline__ void ldmx4t(uint32_t* r, uint32_t addr) {
    asm volatile("ldmatrix.sync.aligned.m8n8.x4.trans.shared.b16 {%0,%1,%2,%3}, [%4];"
        : "=r"(r[0]), "=r"(r[1]), "=r"(r[2]), "=r"(r[3]) : "r"(addr));
}
__device__ __forceinline__ void mma16816(float* d,
    uint32_t a0, uint32_t a1, uint32_t a2, uint32_t a3,
    uint32_t b0, uint32_t b1) {
    asm volatile("mma.sync.aligned.m16n8k16.row.col.f32.f16.f16.f32 "
        "{%0,%1,%2,%3}, {%4,%5,%6,%7}, {%8,%9}, {%0,%1,%2,%3};"
        : "+f"(d[0]), "+f"(d[1]), "+f"(d[2]), "+f"(d[3])
        : "r"(a0), "r"(a1), "r"(a2), "r"(a3), "r"(b0), "r"(b1));
}
__device__ __forceinline__ float ex2f(float x) {
    float y;
    asm("ex2.approx.f32 %0, %1;" : "=f"(y) : "f"(x));
    return y;
}
__device__ __forceinline__ void cp16(uint32_t s, const void* g) {
    asm volatile("cp.async.cg.shared.global [%0], [%1], 16;"
        :: "r"(s), "l"(g) : "memory");
}
#define CP_COMMIT() asm volatile("cp.async.commit_group;" ::: "memory")
#define CP_WAIT0()  asm volatile("cp.async.wait_group 0;" ::: "memory")

#define ROWP 40   // halfs per padded smem row (80 bytes) — conflict-free ldmatrix

// ---------------------------------------------------------------------------
// Kernel 0: fp32 -> fp16 pre-convert of x, qkv_w, proj_w
// ---------------------------------------------------------------------------
__global__ __launch_bounds__(256) void conv_kernel(
    const float* __restrict__ x, const float* __restrict__ w,
    const float* __restrict__ pw)
{
    const int i = (blockIdx.x * 256 + threadIdx.x) * 4;
    const float* src; __half* dst; int off;
    if (i < XE)            { src = x;  dst = g_xh;  off = i; }
    else if (i < XE + WE)  { src = w;  dst = g_wh;  off = i - XE; }
    else                   { src = pw; dst = g_pwh; off = i - XE - WE; }
    float4 v = *(const float4*)&src[off];
    *(__half2*)&dst[off + 0] = __floats2half2_rn(v.x, v.y);
    *(__half2*)&dst[off + 2] = __floats2half2_rn(v.z, v.w);
}

// ---------------------------------------------------------------------------
// Kernel 1: QKV GEMM via mma.sync, cp.async double-buffered, fp16 inputs.
//   q scaled by SCALE*log2e (softmax uses ex2).
// ---------------------------------------------------------------------------
__global__ __launch_bounds__(256) void qkv_mma_kernel(const float* __restrict__ bias)
{
    __shared__ __align__(16) __half Ah[2][128][ROWP];
    __shared__ __align__(16) __half Bh[2][64][ROWP];

    const int tid  = threadIdx.x;
    const int lane = tid & 31;
    const int warp = tid >> 5;
    const int wm   = warp & 3;
    const int wn   = warp >> 2;
    const int m0   = blockIdx.y * 128;
    const int n0   = blockIdx.x * 64;

    const uint32_t a_base0 = smem_u32(&Ah[0][0][0]);
    const uint32_t b_base0 = smem_u32(&Bh[0][0][0]);
    const uint32_t a_stride = 128 * ROWP * 2;
    const uint32_t b_stride = 64 * ROWP * 2;

    float acc[2][4][4];
#pragma unroll
    for (int mt = 0; mt < 2; mt++)
#pragma unroll
        for (int nt = 0; nt < 4; nt++)
#pragma unroll
            for (int i = 0; i < 4; i++) acc[mt][nt][i] = 0.f;

    const int arow = tid >> 1;
    const int ach  = tid & 1;
    const int brow = tid >> 2;
    const int bch  = tid & 3;
    const uint32_t a_so = (uint32_t)arow * 80u + (uint32_t)ach * 32u;
    const uint32_t b_so = (uint32_t)brow * 80u + (uint32_t)bch * 16u;
    const __half* agp = g_xh + (m0 + arow) * C_ + ach * 16;
    const __half* bgp = g_wh + (n0 + brow) * C_ + bch * 8;

#define QKV_STAGE(k0, bufn) do { \
        cp16(a_base0 + (bufn) * a_stride + a_so +  0, agp + (k0));       \
        cp16(a_base0 + (bufn) * a_stride + a_so + 16, agp + (k0) + 8);   \
        cp16(b_base0 + (bufn) * b_stride + b_so,      bgp + (k0));       \
    } while (0)

    QKV_STAGE(0, 0); CP_COMMIT();

    int buf = 0;
#pragma unroll
    for (int it = 0; it < 8; it++) {
        CP_WAIT0();
        __syncthreads();
        if (it < 7) { QKV_STAGE((it + 1) * 32, buf ^ 1); CP_COMMIT(); }

        const uint32_t a_base = a_base0 + (uint32_t)buf * a_stride;
        const uint32_t b_base = b_base0 + (uint32_t)buf * b_stride;
        uint32_t bf[4][4];
#pragma unroll
        for (int nt = 0; nt < 4; nt++) {
            uint32_t addr = b_base
                + (uint32_t)((wn * 32 + nt * 8 + (lane & 7)) * (ROWP * 2))
                + (uint32_t)((lane >> 3) * 16);
            ldmx4(bf[nt], addr);
        }
#pragma unroll
        for (int kk = 0; kk < 2; kk++) {
            uint32_t af[2][4];
#pragma unroll
            for (int mt = 0; mt < 2; mt++) {
                uint32_t addr = a_base
                    + (uint32_t)((wm * 32 + mt * 16 + (lane & 15)) * (ROWP * 2))
                    + (uint32_t)((lane >> 4) * 16 + kk * 32);
                ldmx4(af[mt], addr);
            }
#pragma unroll
            for (int mt = 0; mt < 2; mt++)
#pragma unroll
                for (int nt = 0; nt < 4; nt++)
                    mma16816(acc[mt][nt],
                             af[mt][0], af[mt][1], af[mt][2], af[mt][3],
                             bf[nt][kk * 2], bf[nt][kk * 2 + 1]);
        }
        buf ^= 1;
    }

    const int rA = lane >> 2;
    const int c2 = (lane & 3) * 2;
#pragma unroll
    for (int mt = 0; mt < 2; mt++) {
#pragma unroll
        for (int half8 = 0; half8 < 2; half8++) {
            const int m = m0 + wm * 32 + mt * 16 + half8 * 8 + rA;
            const int bb = m >> 11;
            const int n  = m & (N_ - 1);
#pragma unroll
            for (int nt = 0; nt < 4; nt++) {
                const int o = n0 + wn * 32 + nt * 8 + c2;
                float v0 = acc[mt][nt][half8 * 2 + 0] + bias[o];
                float v1 = acc[mt][nt][half8 * 2 + 1] + bias[o + 1];
                const int which = o >> 8;
                const int h = (o >> 5) & 7;
                const int d = o & 31;
                const int idx = (((bb * H_ + h) * N_) + n) * HD_ + d;
                if (which == 0) { v0 *= QSCALE; v1 *= QSCALE; }
                __half2 hv = __floats2half2_rn(v0, v1);
                if (which == 0)      *(__half2*)&g_qh[idx] = hv;
                else if (which == 1) *(__half2*)&g_kh[idx] = hv;
                else                 *(__half2*)&g_vh[idx] = hv;
            }
        }
    }
}

// ---------------------------------------------------------------------------
// Kernel 2: split-KV mma.sync fp16 flash attention.
//   4 warps / 128 q rows per CTA; blockIdx.z selects key half [z*1024, z*1024+1024).
//   Writes UNNORMALIZED fp32 O partials + l partials; combine kernel finishes.
// ---------------------------------------------------------------------------
#define KT 64
#define KSPLIT 2
#define KEYS_PER_SPLIT (N_ / KSPLIT)   // 1024

__global__ __launch_bounds__(128) void attn_mma_kernel(const float* __restrict__ bt)
{
    __shared__ __align__(16) __half Ks[2][KT][ROWP];
    __shared__ __align__(16) __half Vs[2][KT][ROWP];
    __shared__ float b7s[49];

    const int tid  = threadIdx.x;
    const int lane = tid & 31;
    const int warp = tid >> 5;           // 0..3
    const int bh = blockIdx.y;
    const int q0 = blockIdx.x * 128;
    const int split = blockIdx.z;
    const int t0 = split * KEYS_PER_SPLIT;
    const long base = (long)bh * N_;

    if (tid < 49) b7s[tid] = bt[(tid / 7) - (tid % 7) + 6] * L2E;

    const uint32_t ks_base0 = smem_u32(&Ks[0][0][0]);
    const uint32_t vs_base0 = smem_u32(&Vs[0][0][0]);
    const uint32_t kv_stride = KT * ROWP * 2;

    const int r  = lane >> 2;
    const int cq = lane & 3;
    const int c2 = cq * 2;

    int qa7[2], qb7[2];
    uint32_t qf[2][8];
    int qrA[2];
#pragma unroll
    for (int mt = 0; mt < 2; mt++) {
        qrA[mt] = q0 + warp * 32 + mt * 16 + r;
        const int qrB = qrA[mt] + 8;
        qa7[mt] = (qrA[mt] % 7) * 7;
        qb7[mt] = (qrB % 7) * 7;
        const uint32_t* qpA = (const uint32_t*)(g_qh + (base + qrA[mt]) * HD_);
        const uint32_t* qpB = (const uint32_t*)(g_qh + (base + qrB) * HD_);
        qf[mt][0] = qpA[cq];      qf[mt][1] = qpB[cq];
        qf[mt][2] = qpA[cq + 4];  qf[mt][3] = qpB[cq + 4];
        qf[mt][4] = qpA[cq + 8];  qf[mt][5] = qpB[cq + 8];
        qf[mt][6] = qpA[cq + 12]; qf[mt][7] = qpB[cq + 12];
    }

    float oacc[2][4][4];
#pragma unroll
    for (int mt = 0; mt < 2; mt++)
#pragma unroll
        for (int n = 0; n < 4; n++)
#pragma unroll
            for (int i = 0; i < 4; i++) oacc[mt][n][i] = 0.f;
    float lA[2] = {0.f, 0.f}, lB[2] = {0.f, 0.f};

    const int sj = tid >> 1;
    const int sh = tid & 1;
    const uint32_t s_so = (uint32_t)sj * 80u + (uint32_t)sh * 32u;
    const __half* kgp = g_kh + (base + sj) * HD_ + sh * 16;
    const __half* vgp = g_vh + (base + sj) * HD_ + sh * 16;

#define ATT_STAGE(t, bufn) do { \
        cp16(ks_base0 + (bufn) * kv_stride + s_so +  0, kgp + (long)(t) * HD_);     \
        cp16(ks_base0 + (bufn) * kv_stride + s_so + 16, kgp + (long)(t) * HD_ + 8); \
        cp16(vs_base0 + (bufn) * kv_stride + s_so +  0, vgp + (long)(t) * HD_);     \
        cp16(vs_base0 + (bufn) * kv_stride + s_so + 16, vgp + (long)(t) * HD_ + 8); \
    } while (0)

    ATT_STAGE(t0, 0); CP_COMMIT();

    int buf = 0;
#pragma unroll 1
    for (int it = 0; it < KEYS_PER_SPLIT / KT; it++) {
        CP_WAIT0();
        __syncthreads();
        if (it < KEYS_PER_SPLIT / KT - 1) { ATT_STAGE(t0 + (it + 1) * KT, buf ^ 1); CP_COMMIT(); }

        const int t = t0 + it * KT;
        const uint32_t ks_base = ks_base0 + (uint32_t)buf * kv_stride;
        const uint32_t vs_base = vs_base0 + (uint32_t)buf * kv_stride;

        int jm = (t + c2) % 7;
#pragma unroll
        for (int kt = 0; kt < 4; kt++) {
            uint32_t ph[2][2][2];
#pragma unroll
            for (int jj = 0; jj < 2; jj++) {
                const int jt = kt * 2 + jj;
                uint32_t kf[4];
                uint32_t addr = ks_base + (uint32_t)((jt * 8 + (lane & 7)) * (ROWP * 2))
                              + (uint32_t)((lane >> 3) * 16);
                ldmx4(kf, addr);
                float sa[2][4];
#pragma unroll
                for (int mt = 0; mt < 2; mt++) {
                    sa[mt][0] = sa[mt][1] = sa[mt][2] = sa[mt][3] = 0.f;
                    mma16816(sa[mt], qf[mt][0], qf[mt][1], qf[mt][2], qf[mt][3], kf[0], kf[1]);
                    mma16816(sa[mt], qf[mt][4], qf[mt][5], qf[mt][6], qf[mt][7], kf[2], kf[3]);
                }
                int jm1 = jm + 1; if (jm1 == 7) jm1 = 0;
#pragma unroll
                for (int mt = 0; mt < 2; mt++) {
                    float p0 = ex2f(sa[mt][0] + b7s[qa7[mt] + jm]);
                    float p1 = ex2f(sa[mt][1] + b7s[qa7[mt] + jm1]);
                    float p2 = ex2f(sa[mt][2] + b7s[qb7[mt] + jm]);
                    float p3 = ex2f(sa[mt][3] + b7s[qb7[mt] + jm1]);
                    lA[mt] += p0 + p1;
                    lB[mt] += p2 + p3;
                    __half2 hA = __floats2half2_rn(p0, p1);
                    __half2 hB = __floats2half2_rn(p2, p3);
                    ph[jj][mt][0] = *reinterpret_cast<uint32_t*>(&hA);
                    ph[jj][mt][1] = *reinterpret_cast<uint32_t*>(&hB);
                }
                jm = jm1;
            }
#pragma unroll
            for (int ntp = 0; ntp < 2; ntp++) {
                uint32_t vf[4];
                uint32_t row = (uint32_t)(kt * 16 + ((lane >> 3) & 1) * 8 + (lane & 7));
                uint32_t col = (uint32_t)(ntp * 16 + (lane >> 4) * 8);
                uint32_t addr = vs_base + row * (ROWP * 2) + col * 2;
                ldmx4t(vf, addr);
#pragma unroll
                for (int mt = 0; mt < 2; mt++) {
                    mma16816(oacc[mt][ntp * 2 + 0],
                             ph[0][mt][0], ph[0][mt][1],
                             ph[1][mt][0], ph[1][mt][1],
                             vf[0], vf[1]);
                    mma16816(oacc[mt][ntp * 2 + 1],
                             ph[0][mt][0], ph[0][mt][1],
                             ph[1][mt][0], ph[1][mt][1],
                             vf[2], vf[3]);
                }
            }
        }
        buf ^= 1;
    }

    // write unnormalized partials
#pragma unroll
    for (int mt = 0; mt < 2; mt++) {
        float la = lA[mt], lb = lB[mt];
        la += __shfl_xor_sync(0xffffffffu, la, 1);
        la += __shfl_xor_sync(0xffffffffu, la, 2);
        lb += __shfl_xor_sync(0xffffffffu, lb, 1);
        lb += __shfl_xor_sync(0xffffffffu, lb, 2);
        const long rowA = base + qrA[mt];
        const long rowB = rowA + 8;
        if (cq == 0) {
            g_attL[(long)split * NR + rowA] = la;
            g_attL[(long)split * NR + rowB] = lb;
        }
        float* opA = g_attO + ((long)split * NR + rowA) * HD_;
        float* opB = g_attO + ((long)split * NR + rowB) * HD_;
#pragma unroll
        for (int nt = 0; nt < 4; nt++) {
            *(float2*)&opA[nt * 8 + c2] = make_float2(oacc[mt][nt][0], oacc[mt][nt][1]);
            *(float2*)&opB[nt * 8 + c2] = make_float2(oacc[mt][nt][2], oacc[mt][nt][3]);
        }
    }
}

// ---------------------------------------------------------------------------
// Kernel 2b: combine split-KV partials -> normalized fp16 g_atth.
//   4 threads per row, 8 floats each.
// ---------------------------------------------------------------------------
__global__ __launch_bounds__(256) void combine_kernel()
{
    const int idx = blockIdx.x * 256 + threadIdx.x;   // 0 .. NR*4-1
    const int row = idx >> 2;
    const int ch  = (idx & 3) * 8;
    const float inv = 1.f / (g_attL[row] + g_attL[NR + row]);
    const float4* p0 = (const float4*)(g_attO + (long)row * HD_ + ch);
    const float4* p1 = (const float4*)(g_attO + ((long)NR + row) * HD_ + ch);
    __half* o = g_atth + (long)row * HD_ + ch;
#pragma unroll
    for (int i = 0; i < 2; i++) {
        float4 a = p0[i];
        float4 b = p1[i];
        *(__half2*)&o[i * 4 + 0] = __floats2half2_rn((a.x + b.x) * inv, (a.y + b.y) * inv);
        *(__half2*)&o[i * 4 + 2] = __floats2half2_rn((a.z + b.z) * inv, (a.w + b.w) * inv);
    }
}

// ---------------------------------------------------------------------------
// Kernel 3: proj GEMM via mma.sync, cp.async double-buffered, fp16 inputs.
// ---------------------------------------------------------------------------
__global__ __launch_bounds__(256) void proj_mma_kernel(
    const float* __restrict__ bias, float* __restrict__ out)
{
    __shared__ __align__(16) __half Ah[2][128][ROWP];
    __shared__ __align__(16) __half Bh[2][64][ROWP];

    const int tid  = threadIdx.x;
    const int lane = tid & 31;
    const int warp = tid >> 5;
    const int wm   = warp & 3;
    const int wn   = warp >> 2;
    const int m0   = blockIdx.y * 128;
    const int n0   = blockIdx.x * 64;

    const uint32_t a_base0 = smem_u32(&Ah[0][0][0]);
    const uint32_t b_base0 = smem_u32(&Bh[0][0][0]);
    const uint32_t a_stride = 128 * ROWP * 2;
    const uint32_t b_stride = 64 * ROWP * 2;

    float acc[2][4][4];
#pragma unroll
    for (int mt = 0; mt < 2; mt++)
#pragma unroll
        for (int nt = 0; nt < 4; nt++)
#pragma unroll
            for (int i = 0; i < 4; i++) acc[mt][nt][i] = 0.f;

    const int arow = tid >> 1;
    const int ach  = tid & 1;
    const int brow = tid >> 2;
    const int bch  = tid & 3;
    const uint32_t a_so = (uint32_t)arow * 80u + (uint32_t)ach * 32u;
    const uint32_t b_so = (uint32_t)brow * 80u + (uint32_t)bch * 16u;

    const int m  = m0 + arow;
    const int bb = m >> 11;
    const int nn = m & (N_ - 1);
    const __half* agp = g_atth + ((long)bb * H_ * N_ + nn) * HD_ + ach * 16;
    const __half* bgp = g_pwh + (n0 + brow) * C_ + bch * 8;

#define PROJ_STAGE(h, bufn) do { \
        cp16(a_base0 + (bufn) * a_stride + a_so +  0, agp + (long)(h) * N_ * HD_);     \
        cp16(a_base0 + (bufn) * a_stride + a_so + 16, agp + (long)(h) * N_ * HD_ + 8); \
        cp16(b_base0 + (bufn) * b_stride + b_so,      bgp + (h) * 32);                 \
    } while (0)

    PROJ_STAGE(0, 0); CP_COMMIT();

    int buf = 0;
#pragma unroll
    for (int it = 0; it < 8; it++) {
        CP_WAIT0();
        __syncthreads();
        if (it < 7) { PROJ_STAGE(it + 1, buf ^ 1); CP_COMMIT(); }

        const uint32_t a_base = a_base0 + (uint32_t)buf * a_stride;
        const uint32_t b_base = b_base0 + (uint32_t)buf * b_stride;
        uint32_t bf[4][4];
#pragma unroll
        for (int nt = 0; nt < 4; nt++) {
            uint32_t addr = b_base
                + (uint32_t)((wn * 32 + nt * 8 + (lane & 7)) * (ROWP * 2))
                + (uint32_t)((lane >> 3) * 16);
            ldmx4(bf[nt], addr);
        }
#pragma unroll
        for (int kk = 0; kk < 2; kk++) {
            uint32_t af[2][4];
#pragma unroll
            for (int mt = 0; mt < 2; mt++) {
                uint32_t addr = a_base
                    + (uint32_t)((wm * 32 + mt * 16 + (lane & 15)) * (ROWP * 2))
                    + (uint32_t)((lane >> 4) * 16 + kk * 32);
                ldmx4(af[mt], addr);
            }
#pragma unroll
            for (int mt = 0; mt < 2; mt++)
#pragma unroll
                for (int nt = 0; nt < 4; nt++)
                    mma16816(acc[mt][nt],
                             af[mt][0], af[mt][1], af[mt][2], af[mt][3],
                             bf[nt][kk * 2], bf[nt][kk * 2 + 1]);
        }
        buf ^= 1;
    }

    const int rA = lane >> 2;
    const int c2 = (lane & 3) * 2;
#pragma unroll
    for (int mt = 0; mt < 2; mt++) {
#pragma unroll
        for (int half8 = 0; half8 < 2; half8++) {
            const int mm = m0 + wm * 32 + mt * 16 + half8 * 8 + rA;
#pragma unroll
            for (int nt = 0; nt < 4; nt++) {
                const int o = n0 + wn * 32 + nt * 8 + c2;
                float2 v;
                v.x = acc[mt][nt][half8 * 2 + 0] + bias[o];
                v.y = acc[mt][nt][half8 * 2 + 1] + bias[o + 1];
                *(float2*)&out[mm * C_ + o] = v;
            }
        }
    }
}

// ---------------------------------------------------------------------------
// Launch
// ---------------------------------------------------------------------------
extern "C" void kernel_launch(void* const* d_in, const int* in_sizes, int n_in,
                              void* d_out, int out_size)
{
    const float* x      = (const float*)d_in[0];
    const float* qkv_w  = (const float*)d_in[1];
    const float* qkv_b  = (const float*)d_in[2];
    const float* proj_w = (const float*)d_in[3];
    const float* proj_b = (const float*)d_in[4];
    const float* btab   = (const float*)d_in[5];
    float* out = (float*)d_out;

    (void)in_sizes; (void)n_in; (void)out_size;

    conv_kernel<<<(XE + WE + PE) / (256 * 4), 256>>>(x, qkv_w, proj_w);

    dim3 g1(QKV_OUT / 64, M_ / 128);       // (12, 64)
    qkv_mma_kernel<<<g1, 256>>>(qkv_b);

    dim3 g2(N_ / 128, B_ * H_, KSPLIT);    // (16, 32, 2) = 1024 CTAs
    attn_mma_kernel<<<g2, 128>>>(btab);

    combine_kernel<<<NR * 4 / 256, 256>>>();   // 1024 blocks

    dim3 g3(C_ / 64, M_ / 128);            // (4, 64)
    proj_mma_kernel<<<g3, 256>>>(proj_b, out);
}